// round 2
// baseline (speedup 1.0000x reference)
#include <cuda_runtime.h>

#define E_TOTAL   20000
#define FDIM      17
#define TILE_E    40
#define CO_TILE   4            // co channels per CTA (grid.y = 8)
#define W3S_ROWS  384          // CO_TILE*32*3
#define W3S_PITCH 33           // padded row -> conflict-free smem reads
#define EC        8            // edges buffered per output chunk
#define ROWS_CTA  (CO_TILE*3)  // 12 output rows per CTA
#define EDGE_FLTS (ROWS_CTA*96)   // 1152 floats per edge per CTA
#define SMEM_FLOATS (W3S_ROWS*W3S_PITCH + TILE_E*32 + TILE_E*27 + EC*EDGE_FLTS)
#define SMEM_BYTES  (SMEM_FLOATS * 4)

typedef unsigned long long ull;

__device__ __forceinline__ void ffma2(ull& d, ull a, ull b) {
    asm("fma.rn.f32x2 %0, %1, %2, %0;" : "+l"(d) : "l"(a), "l"(b));
}
__device__ __forceinline__ ull pk2(float lo, float hi) {
    ull r; asm("mov.b64 %0, {%1, %2};" : "=l"(r) : "f"(lo), "f"(hi)); return r;
}
__device__ __forceinline__ float hsum2(ull v) {
    float a, b; asm("mov.b64 {%0, %1}, %2;" : "=f"(a), "=f"(b) : "l"(v));
    return a + b;
}

// scratch for h2 (radial MLP output), allocation-free per harness rules
__device__ float g_h[E_TOTAL * 32];

// ---------------------------------------------------------------------------
// Kernel 1: radial MLP  f[E,17] -> h2[E,32]. One warp per edge.
// ---------------------------------------------------------------------------
__global__ __launch_bounds__(256) void mlp_kernel(
    const float* __restrict__ f,
    const float* __restrict__ w1, const float* __restrict__ b1,
    const float* __restrict__ g1, const float* __restrict__ be1,
    const float* __restrict__ w2, const float* __restrict__ b2,
    const float* __restrict__ g2, const float* __restrict__ be2)
{
    __shared__ float w1s[32 * FDIM];
    __shared__ float w2s[32 * 33];
    __shared__ float b1s[32], g1s[32], be1s[32];
    __shared__ float b2s[32], g2s[32], be2s[32];

    int tid = threadIdx.x;
    for (int i = tid; i < 32 * FDIM; i += 256) w1s[i] = w1[i];
    for (int i = tid; i < 32 * 32;  i += 256) w2s[(i >> 5) * 33 + (i & 31)] = w2[i];
    if (tid < 32) {
        b1s[tid] = b1[tid]; g1s[tid] = g1[tid]; be1s[tid] = be1[tid];
        b2s[tid] = b2[tid]; g2s[tid] = g2[tid]; be2s[tid] = be2[tid];
    }
    __syncthreads();

    int warp = tid >> 5, lane = tid & 31;
    int e = blockIdx.x * 8 + warp;
    if (e >= E_TOTAL) return;

    float fv = (lane < FDIM) ? f[e * FDIM + lane] : 0.0f;
    float h = b1s[lane];
    #pragma unroll
    for (int k = 0; k < FDIM; k++) {
        float fk = __shfl_sync(0xffffffffu, fv, k);
        h = fmaf(fk, w1s[lane * FDIM + k], h);
    }
    float s = h;
    #pragma unroll
    for (int o = 16; o > 0; o >>= 1) s += __shfl_xor_sync(0xffffffffu, s, o);
    float mu = s * (1.0f / 32.0f);
    float d = h - mu;
    float v = d * d;
    #pragma unroll
    for (int o = 16; o > 0; o >>= 1) v += __shfl_xor_sync(0xffffffffu, v, o);
    float x = d * rsqrtf(v * (1.0f / 32.0f) + 1e-5f) * g1s[lane] + be1s[lane];
    x = fmaxf(x, 0.0f);

    float h2 = b2s[lane];
    #pragma unroll
    for (int k = 0; k < 32; k++) {
        float xk = __shfl_sync(0xffffffffu, x, k);
        h2 = fmaf(xk, w2s[lane * 33 + k], h2);
    }
    s = h2;
    #pragma unroll
    for (int o = 16; o > 0; o >>= 1) s += __shfl_xor_sync(0xffffffffu, s, o);
    mu = s * (1.0f / 32.0f);
    d = h2 - mu;
    v = d * d;
    #pragma unroll
    for (int o = 16; o > 0; o >>= 1) v += __shfl_xor_sync(0xffffffffu, v, o);
    float x2 = d * rsqrtf(v * (1.0f / 32.0f) + 1e-5f) * g2s[lane] + be2s[lane];
    x2 = fmaxf(x2, 0.0f);

    g_h[e * 32 + lane] = x2;
}

// ---------------------------------------------------------------------------
// Kernel 2: r = h2 @ w3.T + b3 fused with the frequency contraction.
// grid = (E/TILE_E, 32/CO_TILE). 256 threads = (edge-half, co_rel, ci).
// GEMM uses packed fma.rn.f32x2 over the k-dimension; epilogue bounces
// through smem (conflict-free STS) and copies out as coalesced float4.
// ---------------------------------------------------------------------------
__global__ __launch_bounds__(256, 2) void conv_kernel(
    const float* __restrict__ basis,
    const float* __restrict__ w3,
    const float* __restrict__ b3,
    float* __restrict__ out)
{
    extern __shared__ float smem[];
    float* ws    = smem;                            // 384 * 33
    float* h_s   = ws + W3S_ROWS * W3S_PITCH;       // 40 * 32
    float* B_s   = h_s + TILE_E * 32;               // 40 * 27
    float* out_s = B_s + TILE_E * 27;               // EC * 1152

    int tid = threadIdx.x;
    int e0  = blockIdx.x * TILE_E;
    int cy  = blockIdx.y;                           // 0..7

    // stage w3 slice [cy*384, +384) rows (coalesced gmem, padded smem)
    const float* w3g = w3 + (size_t)cy * (W3S_ROWS * 32);
    for (int i = tid; i < W3S_ROWS * 32; i += 256)
        ws[(i >> 5) * W3S_PITCH + (i & 31)] = w3g[i];
    for (int i = tid; i < TILE_E * 32; i += 256)
        h_s[i] = g_h[(size_t)e0 * 32 + i];
    for (int i = tid; i < TILE_E * 27; i += 256)
        B_s[i] = basis[(size_t)e0 * 27 + i];
    __syncthreads();

    int eh   = tid >> 7;            // edge-half within pair
    int co_r = (tid >> 5) & 3;      // co within CTA tile
    int ci   = tid & 31;
    int row0 = (co_r * 32 + ci) * 3;

    // register-cache this thread's 3 w3 rows, packed into f32x2 pairs
    ull w3p[48];
    #pragma unroll
    for (int f = 0; f < 3; f++) {
        const float* wr = ws + (row0 + f) * W3S_PITCH;   // stride-99 -> no conflict
        #pragma unroll
        for (int kp = 0; kp < 16; kp++)
            w3p[f * 16 + kp] = pk2(wr[2 * kp], wr[2 * kp + 1]);
    }

    int co = cy * CO_TILE + co_r;
    size_t jb = ((size_t)co * 32 + ci) * 3;
    ull bias0 = pk2(b3[jb],     0.0f);
    ull bias1 = pk2(b3[jb + 1], 0.0f);
    ull bias2 = pk2(b3[jb + 2], 0.0f);

    for (int ch = 0; ch < TILE_E / EC; ch++) {
        // ---- compute EC edges (each thread does its edge-half) ----
        #pragma unroll
        for (int ep = 0; ep < EC / 2; ep++) {
            int slot = ep * 2 + eh;
            int el   = ch * EC + slot;

            ull a0 = bias0, a1 = bias1, a2 = bias2;
            const ulonglong2* hp = reinterpret_cast<const ulonglong2*>(h_s + el * 32);
            #pragma unroll
            for (int q = 0; q < 8; q++) {
                ulonglong2 hv = hp[q];
                ffma2(a0, hv.x, w3p[ 0 + 2 * q]); ffma2(a0, hv.y, w3p[ 0 + 2 * q + 1]);
                ffma2(a1, hv.x, w3p[16 + 2 * q]); ffma2(a1, hv.y, w3p[16 + 2 * q + 1]);
                ffma2(a2, hv.x, w3p[32 + 2 * q]); ffma2(a2, hv.y, w3p[32 + 2 * q + 1]);
            }
            float R0 = hsum2(a0), R1 = hsum2(a1), R2 = hsum2(a2);

            const float* Bp = B_s + el * 27;
            float* os = out_s + slot * EDGE_FLTS + (co_r * 3) * 96 + ci * 3;
            #pragma unroll
            for (int dd = 0; dd < 3; dd++)
                #pragma unroll
                for (int di = 0; di < 3; di++) {
                    float vv = fmaf(R2, Bp[dd * 9 + di * 3 + 2],
                               fmaf(R1, Bp[dd * 9 + di * 3 + 1],
                                    R0 * Bp[dd * 9 + di * 3 + 0]));
                    os[dd * 96 + di] = vv;   // lane stride 3 -> conflict-free
                }
        }
        __syncthreads();

        // ---- coalesced copy-out: EC edges * 1152 floats = 2304 float4 ----
        const float4* src = reinterpret_cast<const float4*>(out_s);
        float4* dstb = reinterpret_cast<float4*>(
            out + (size_t)(e0 + ch * EC) * 9216 + (size_t)cy * EDGE_FLTS);
        #pragma unroll
        for (int it = 0; it < (EC * EDGE_FLTS / 4) / 256; it++) {
            int i  = it * 256 + tid;
            int el = i / (EDGE_FLTS / 4);        // edge within chunk
            int j  = i % (EDGE_FLTS / 4);        // float4 within edge slab
            dstb[(size_t)el * (9216 / 4) + j] = src[i];
        }
        __syncthreads();
    }
}

// ---------------------------------------------------------------------------
extern "C" void kernel_launch(void* const* d_in, const int* in_sizes, int n_in,
                              void* d_out, int out_size)
{
    const float* f     = (const float*)d_in[0];
    const float* basis = (const float*)d_in[1];
    const float* w1    = (const float*)d_in[2];
    const float* b1    = (const float*)d_in[3];
    const float* g1    = (const float*)d_in[4];
    const float* be1   = (const float*)d_in[5];
    const float* w2    = (const float*)d_in[6];
    const float* b2    = (const float*)d_in[7];
    const float* g2    = (const float*)d_in[8];
    const float* be2   = (const float*)d_in[9];
    const float* w3    = (const float*)d_in[10];
    const float* b3    = (const float*)d_in[11];
    float* out = (float*)d_out;

    mlp_kernel<<<(E_TOTAL + 7) / 8, 256>>>(f, w1, b1, g1, be1, w2, b2, g2, be2);

    cudaFuncSetAttribute(conv_kernel,
                         cudaFuncAttributeMaxDynamicSharedMemorySize, SMEM_BYTES);
    dim3 grid(E_TOTAL / TILE_E, 32 / CO_TILE);
    conv_kernel<<<grid, 256, SMEM_BYTES>>>(basis, w3, b3, out);
}

// round 7
// speedup vs baseline: 1.1753x; 1.1753x over previous
#include <cuda_runtime.h>

#define E_TOTAL   20000
#define FDIM      17
#define TILE_E    40
#define CO_TILE   8
#define W3S_ROWS  768          // CO_TILE*32*3
#define W3S_PITCH 33           // padded row (stride 33 -> conflict-free)
#define SMEM_FLOATS (W3S_ROWS*W3S_PITCH + TILE_E*32 + TILE_E*27)
#define SMEM_BYTES  (SMEM_FLOATS * 4)

// scratch for h2 (radial MLP output), allocation-free per harness rules
__device__ float g_h[E_TOTAL * 32];

// ---------------------------------------------------------------------------
// Kernel 1: radial MLP  f[E,17] -> h2[E,32]. One warp per edge.
// ---------------------------------------------------------------------------
__global__ __launch_bounds__(256) void mlp_kernel(
    const float* __restrict__ f,
    const float* __restrict__ w1, const float* __restrict__ b1,
    const float* __restrict__ g1, const float* __restrict__ be1,
    const float* __restrict__ w2, const float* __restrict__ b2,
    const float* __restrict__ g2, const float* __restrict__ be2)
{
    __shared__ float w1s[32 * FDIM];
    __shared__ float w2s[32 * 33];
    __shared__ float b1s[32], g1s[32], be1s[32];
    __shared__ float b2s[32], g2s[32], be2s[32];

    int tid = threadIdx.x;
    for (int i = tid; i < 32 * FDIM; i += 256) w1s[i] = w1[i];
    for (int i = tid; i < 32 * 32;  i += 256) w2s[(i >> 5) * 33 + (i & 31)] = w2[i];
    if (tid < 32) {
        b1s[tid] = b1[tid]; g1s[tid] = g1[tid]; be1s[tid] = be1[tid];
        b2s[tid] = b2[tid]; g2s[tid] = g2[tid]; be2s[tid] = be2[tid];
    }
    __syncthreads();

    int warp = tid >> 5, lane = tid & 31;
    int e = blockIdx.x * 8 + warp;
    if (e >= E_TOTAL) return;

    float fv = (lane < FDIM) ? f[e * FDIM + lane] : 0.0f;
    float h = b1s[lane];
    #pragma unroll
    for (int k = 0; k < FDIM; k++) {
        float fk = __shfl_sync(0xffffffffu, fv, k);
        h = fmaf(fk, w1s[lane * FDIM + k], h);
    }
    float s = h;
    #pragma unroll
    for (int o = 16; o > 0; o >>= 1) s += __shfl_xor_sync(0xffffffffu, s, o);
    float mu = s * (1.0f / 32.0f);
    float d = h - mu;
    float v = d * d;
    #pragma unroll
    for (int o = 16; o > 0; o >>= 1) v += __shfl_xor_sync(0xffffffffu, v, o);
    float x = d * rsqrtf(v * (1.0f / 32.0f) + 1e-5f) * g1s[lane] + be1s[lane];
    x = fmaxf(x, 0.0f);

    float h2 = b2s[lane];
    #pragma unroll
    for (int k = 0; k < 32; k++) {
        float xk = __shfl_sync(0xffffffffu, x, k);
        h2 = fmaf(xk, w2s[lane * 33 + k], h2);
    }
    s = h2;
    #pragma unroll
    for (int o = 16; o > 0; o >>= 1) s += __shfl_xor_sync(0xffffffffu, s, o);
    mu = s * (1.0f / 32.0f);
    d = h2 - mu;
    v = d * d;
    #pragma unroll
    for (int o = 16; o > 0; o >>= 1) v += __shfl_xor_sync(0xffffffffu, v, o);
    float x2 = d * rsqrtf(v * (1.0f / 32.0f) + 1e-5f) * g2s[lane] + be2s[lane];
    x2 = fmaxf(x2, 0.0f);

    g_h[e * 32 + lane] = x2;
}

// ---------------------------------------------------------------------------
// Kernel 2: r = h2 @ w3.T + b3 fused with the frequency contraction.
// grid = (E/TILE_E, 32/CO_TILE). 256 threads; thread = (co_rel, ci) pair.
// Epilogue: shuffle-transpose R within the warp so every STG.32 is
// fully coalesced (lane l stores columns l, l+32, l+64 of each row).
// ---------------------------------------------------------------------------
__global__ __launch_bounds__(256, 2) void conv_kernel(
    const float* __restrict__ basis,
    const float* __restrict__ w3,
    const float* __restrict__ b3,
    float* __restrict__ out)
{
    extern __shared__ float smem[];
    float* w3s = smem;                           // 768 * 33
    float* h_s = smem + W3S_ROWS * W3S_PITCH;    // TILE_E * 32
    float* B_s = h_s + TILE_E * 32;              // TILE_E * 27

    int tid = threadIdx.x;
    int e0  = blockIdx.x * TILE_E;
    int cy  = blockIdx.y;                        // co tile index (0..3)

    const float* w3g = w3 + (size_t)cy * (W3S_ROWS * 32);
    for (int i = tid; i < W3S_ROWS * 32; i += 256)
        w3s[(i >> 5) * W3S_PITCH + (i & 31)] = w3g[i];
    for (int i = tid; i < TILE_E * 32; i += 256)
        h_s[i] = g_h[(size_t)e0 * 32 + i];
    for (int i = tid; i < TILE_E * 27; i += 256)
        B_s[i] = basis[(size_t)e0 * 27 + i];
    __syncthreads();

    int co_r = tid >> 5, ci = tid & 31;
    int co = cy * CO_TILE + co_r;

    // register-cache this thread's 3 w3 rows (96 floats); stride 99 == 3 mod 32
    float w3r[96];
    #pragma unroll
    for (int ff = 0; ff < 3; ff++)
        #pragma unroll
        for (int k = 0; k < 32; k++)
            w3r[ff * 32 + k] = w3s[(tid * 3 + ff) * W3S_PITCH + k];

    size_t jb = ((size_t)co * 32 + ci) * 3;
    float b30 = b3[jb], b31 = b3[jb + 1], b32 = b3[jb + 2];

    // hoisted epilogue shuffle plan: lane stores columns ci, ci+32, ci+64
    int srcL[3], diL[3];
    #pragma unroll
    for (int m = 0; m < 3; m++) {
        int c = ci + 32 * m;
        srcL[m] = c / 3;
        diL[m]  = c - srcL[m] * 3;
    }

    // warp's output base: row block (co*3), column 0
    float* outb = out + (size_t)e0 * 9216 + (size_t)(co * 3) * 96;

    for (int e = 0; e < TILE_E; e++) {
        const float* hp = h_s + e * 32;
        float R0 = b30, R1 = b31, R2 = b32;
        #pragma unroll
        for (int k4 = 0; k4 < 8; k4++) {
            float4 hv = *reinterpret_cast<const float4*>(hp + k4 * 4);
            R0 = fmaf(hv.x, w3r[0 * 32 + k4 * 4 + 0], R0);
            R1 = fmaf(hv.x, w3r[1 * 32 + k4 * 4 + 0], R1);
            R2 = fmaf(hv.x, w3r[2 * 32 + k4 * 4 + 0], R2);
            R0 = fmaf(hv.y, w3r[0 * 32 + k4 * 4 + 1], R0);
            R1 = fmaf(hv.y, w3r[1 * 32 + k4 * 4 + 1], R1);
            R2 = fmaf(hv.y, w3r[2 * 32 + k4 * 4 + 1], R2);
            R0 = fmaf(hv.z, w3r[0 * 32 + k4 * 4 + 2], R0);
            R1 = fmaf(hv.z, w3r[1 * 32 + k4 * 4 + 2], R1);
            R2 = fmaf(hv.z, w3r[2 * 32 + k4 * 4 + 2], R2);
            R0 = fmaf(hv.w, w3r[0 * 32 + k4 * 4 + 3], R0);
            R1 = fmaf(hv.w, w3r[1 * 32 + k4 * 4 + 3], R1);
            R2 = fmaf(hv.w, w3r[2 * 32 + k4 * 4 + 3], R2);
        }

        const float* Bp = B_s + e * 27;
        float* op = outb + (size_t)e * 9216;
        #pragma unroll
        for (int m = 0; m < 3; m++) {
            // fetch the R triple that owns column (ci + 32*m)
            float S0 = __shfl_sync(0xffffffffu, R0, srcL[m]);
            float S1 = __shfl_sync(0xffffffffu, R1, srcL[m]);
            float S2 = __shfl_sync(0xffffffffu, R2, srcL[m]);
            int di = diL[m];
            int c  = ci + 32 * m;
            #pragma unroll
            for (int dd = 0; dd < 3; dd++) {
                const float* Bq = Bp + dd * 9 + di * 3;
                float vv = fmaf(S2, Bq[2], fmaf(S1, Bq[1], S0 * Bq[0]));
                op[dd * 96 + c] = vv;        // 32 consecutive floats per warp
            }
        }
    }
}

// ---------------------------------------------------------------------------
extern "C" void kernel_launch(void* const* d_in, const int* in_sizes, int n_in,
                              void* d_out, int out_size)
{
    const float* f     = (const float*)d_in[0];
    const float* basis = (const float*)d_in[1];
    const float* w1    = (const float*)d_in[2];
    const float* b1    = (const float*)d_in[3];
    const float* g1    = (const float*)d_in[4];
    const float* be1   = (const float*)d_in[5];
    const float* w2    = (const float*)d_in[6];
    const float* b2    = (const float*)d_in[7];
    const float* g2    = (const float*)d_in[8];
    const float* be2   = (const float*)d_in[9];
    const float* w3    = (const float*)d_in[10];
    const float* b3    = (const float*)d_in[11];
    float* out = (float*)d_out;

    mlp_kernel<<<(E_TOTAL + 7) / 8, 256>>>(f, w1, b1, g1, be1, w2, b2, g2, be2);

    cudaFuncSetAttribute(conv_kernel,
                         cudaFuncAttributeMaxDynamicSharedMemorySize, SMEM_BYTES);
    dim3 grid(E_TOTAL / TILE_E, 32 / CO_TILE);
    conv_kernel<<<grid, 256, SMEM_BYTES>>>(basis, w3, b3, out);
}